// round 4
// baseline (speedup 1.0000x reference)
#include <cuda_runtime.h>
#include <cuda_fp16.h>
#include <math.h>

constexpr int B  = 32;
constexpr int N  = 4096;
constexpr int DK = 128;
constexpr int H  = 128;
constexpr int A  = 128;
constexpr int NSPLIT = 32;          // attention blocks per batch row
constexpr int CHUNK  = N / NSPLIT;  // 128
constexpr int NFIN   = 16;          // finish blocks per batch row

// ---------------- scratch (device globals) ----------------
__device__ uint2 g_zfea[(size_t)B * N * 32];    // fp16 encoder features (4 halves/uint2)
__device__ float g_e[B * N];
__device__ float g_cov[B * N];
__device__ float g_h[B * H], g_c[B * H];
__device__ float g_s[B * DK];
__device__ float g_dec[B * A];
__device__ float g_mp[B * NSPLIT], g_lp[B * NSPLIT];
__device__ float g_ctxp[(size_t)B * NSPLIT * DK];
__device__ float g_closs[B];

__device__ __forceinline__ float tanh_fast(float x) {
    float y;
    asm("tanh.approx.f32 %0, %1;" : "=f"(y) : "f"(x));
    return y;
}
__device__ __forceinline__ float sigf(float x) { return 1.f / (1.f + __expf(-x)); }

// ---------------- init ----------------
__global__ void k_init(const float* __restrict__ h0, const float* __restrict__ c0) {
    int i = blockIdx.x * blockDim.x + threadIdx.x;
    if (i < B * H) { g_h[i] = h0[i]; g_c[i] = c0[i]; g_s[i] = 0.f; }
    if (i < B) g_closs[i] = 0.f;
    for (int j = i; j < B * N; j += gridDim.x * blockDim.x) g_cov[j] = 0.f;
}

// ---------------- z_fea = z @ W_z, stored fp16 ----------------
__global__ void __launch_bounds__(256) k_zfea(const float* __restrict__ Z,
                                              const float* __restrict__ Wz) {
    __shared__ float z_s[128][17];
    __shared__ float w_s[16][128];
    const int tid  = threadIdx.x;
    const int rbase = blockIdx.x * 128;
    const int rowg = tid >> 4;
    const int colg = tid & 15;

    float acc[8][8];
#pragma unroll
    for (int i = 0; i < 8; ++i)
#pragma unroll
        for (int j = 0; j < 8; ++j) acc[i][j] = 0.f;

    for (int kk = 0; kk < 128; kk += 16) {
        {
            int r = tid >> 1;
            int c = (tid & 1) * 8;
            const float* src = Z + (size_t)(rbase + r) * 128 + kk + c;
            float4 a0 = *(const float4*)(src);
            float4 a1 = *(const float4*)(src + 4);
            z_s[r][c + 0] = a0.x; z_s[r][c + 1] = a0.y; z_s[r][c + 2] = a0.z; z_s[r][c + 3] = a0.w;
            z_s[r][c + 4] = a1.x; z_s[r][c + 5] = a1.y; z_s[r][c + 6] = a1.z; z_s[r][c + 7] = a1.w;
        }
        {
            int kr = tid >> 4;
            int c  = (tid & 15) * 8;
            const float* src = Wz + (size_t)(kk + kr) * 128 + c;
            *(float4*)&w_s[kr][c]     = *(const float4*)(src);
            *(float4*)&w_s[kr][c + 4] = *(const float4*)(src + 4);
        }
        __syncthreads();
#pragma unroll
        for (int k = 0; k < 16; ++k) {
            float za[8];
#pragma unroll
            for (int i = 0; i < 8; ++i) za[i] = z_s[rowg * 8 + i][k];
            float4 wb0 = *(const float4*)&w_s[k][colg * 8];
            float4 wb1 = *(const float4*)&w_s[k][colg * 8 + 4];
            float wb[8] = {wb0.x, wb0.y, wb0.z, wb0.w, wb1.x, wb1.y, wb1.z, wb1.w};
#pragma unroll
            for (int i = 0; i < 8; ++i)
#pragma unroll
                for (int j = 0; j < 8; ++j) acc[i][j] = fmaf(za[i], wb[j], acc[i][j]);
        }
        __syncthreads();
    }
#pragma unroll
    for (int i = 0; i < 8; ++i) {
        size_t r = rbase + rowg * 8 + i;
        __half2 p0 = __floats2half2_rn(acc[i][0], acc[i][1]);
        __half2 p1 = __floats2half2_rn(acc[i][2], acc[i][3]);
        __half2 p2 = __floats2half2_rn(acc[i][4], acc[i][5]);
        __half2 p3 = __floats2half2_rn(acc[i][6], acc[i][7]);
        uint2 u0, u1;
        u0.x = *reinterpret_cast<unsigned*>(&p0);
        u0.y = *reinterpret_cast<unsigned*>(&p1);
        u1.x = *reinterpret_cast<unsigned*>(&p2);
        u1.y = *reinterpret_cast<unsigned*>(&p3);
        g_zfea[r * 32 + colg * 2]     = u0;
        g_zfea[r * 32 + colg * 2 + 1] = u1;
    }
}

// ---------------- LSTM cell + dec_fea ----------------
__device__ __forceinline__ void lstm_and_dec(
    int b, int tid,
    const float* __restrict__ Wih, const float* __restrict__ Whh,
    const float* __restrict__ bih, const float* __restrict__ bhh,
    const float* __restrict__ Wx,  const float* __restrict__ battn,
    float* sh)
{
    float* sh_s = sh;           // 128
    float* sh_h = sh + 128;     // 128
    float* sh_c = sh + 256;     // 128
    float* sh_part = sh + 384;  // 1024
    float* sh_hn = sh + 1408;   // 128
    float* sh_cn = sh + 1536;   // 128

    if (tid < 128) {
        sh_s[tid] = g_s[b * DK + tid];
        sh_h[tid] = g_h[b * H + tid];
        sh_c[tid] = g_c[b * H + tid];
    }
    __syncthreads();

    const int j = tid & 127;
    const int half = tid >> 7;
    const float* xv = half ? sh_h : sh_s;
    const float* Wb = half ? Whh : Wih;
#pragma unroll
    for (int g = 0; g < 4; ++g) {
        const float4* wr = (const float4*)(Wb + (size_t)(g * 128 + j) * 128);
        float acc = 0.f;
#pragma unroll 8
        for (int d = 0; d < 32; ++d) {
            float4 w = wr[d];
            acc = fmaf(w.x, xv[4 * d + 0], acc);
            acc = fmaf(w.y, xv[4 * d + 1], acc);
            acc = fmaf(w.z, xv[4 * d + 2], acc);
            acc = fmaf(w.w, xv[4 * d + 3], acc);
        }
        sh_part[half * 512 + g * 128 + j] = acc;
    }
    __syncthreads();

    if (tid < 128) {
        float gi = sh_part[0   + tid] + sh_part[512 + tid] + bih[tid]       + bhh[tid];
        float gf = sh_part[128 + tid] + sh_part[640 + tid] + bih[128 + tid] + bhh[128 + tid];
        float gg = sh_part[256 + tid] + sh_part[768 + tid] + bih[256 + tid] + bhh[256 + tid];
        float go = sh_part[384 + tid] + sh_part[896 + tid] + bih[384 + tid] + bhh[384 + tid];
        float cn = sigf(gf) * sh_c[tid] + sigf(gi) * tanhf(gg);
        float hn = sigf(go) * tanhf(cn);
        sh_hn[tid] = hn; sh_cn[tid] = cn;
        g_h[b * H + tid] = hn;
        g_c[b * H + tid] = cn;
    }
    __syncthreads();

    if (tid < 128) {
        float acc = battn[tid];
#pragma unroll 4
        for (int k = 0; k < 128; ++k) {
            acc = fmaf(sh_hn[k], Wx[(size_t)k * A + tid], acc);
            acc = fmaf(sh_cn[k], Wx[(size_t)(128 + k) * A + tid], acc);
        }
        g_dec[b * A + tid] = acc;
    }
}

__global__ void __launch_bounds__(256) k_lstm0(
    const float* __restrict__ Wih, const float* __restrict__ Whh,
    const float* __restrict__ bih, const float* __restrict__ bhh,
    const float* __restrict__ Wx,  const float* __restrict__ battn)
{
    __shared__ float sh[1664];
    lstm_and_dec(blockIdx.x, threadIdx.x, Wih, Whh, bih, bhh, Wx, battn, sh);
}

// ---------------- attention main pass ----------------
__global__ void __launch_bounds__(256, 5) k_attn(
    const float* __restrict__ Z, const float* __restrict__ mask,
    const float* __restrict__ wc, const float* __restrict__ v)
{
    const int b = blockIdx.y;
    const int split = blockIdx.x;
    const int nbase = split * CHUNK;
    const int tid = threadIdx.x;
    const int lane = tid & 31;
    const int warp = tid >> 5;

    __shared__ float sh_cov[CHUNK];
    __shared__ float sh_msk[CHUNK];
    __shared__ float sh_wm[8], sh_wl[8];
    __shared__ float sh_wctx[8][128];

    if (tid < CHUNK) {
        sh_cov[tid] = g_cov[b * N + nbase + tid];
        sh_msk[tid] = mask[b * N + nbase + tid];
    }
    const float4 dec4 = ((const float4*)(g_dec + b * A))[lane];
    const float4 wc4  = ((const float4*)wc)[lane];
    const float4 v4   = ((const float4*)v)[lane];
    __syncthreads();

    float m = -3.0e38f, l = 0.f;
    float4 ctx = {0.f, 0.f, 0.f, 0.f};

    const uint2*  zfb = g_zfea + (size_t)b * N * 32;
    const float4* zb  = (const float4*)Z + (size_t)b * N * 32;

    const int nloc0 = warp * 16;
    // depth-2 prefetch: 4 loads in flight per warp
    uint2  zf[2];
    float4 zv[2];
    zf[0] = zfb[(size_t)(nbase + nloc0 + 0) * 32 + lane];
    zv[0] = zb [(size_t)(nbase + nloc0 + 0) * 32 + lane];
    zf[1] = zfb[(size_t)(nbase + nloc0 + 1) * 32 + lane];
    zv[1] = zb [(size_t)(nbase + nloc0 + 1) * 32 + lane];

#pragma unroll
    for (int i = 0; i < 16; ++i) {
        const int nloc = nloc0 + i;
        uint2  zfu = zf[i & 1];
        float4 zv_c = zv[i & 1];
        if (i < 14) {
            zf[i & 1] = zfb[(size_t)(nbase + nloc + 2) * 32 + lane];
            zv[i & 1] = zb [(size_t)(nbase + nloc + 2) * 32 + lane];
        }
        __half2 ha = *reinterpret_cast<__half2*>(&zfu.x);
        __half2 hb = *reinterpret_cast<__half2*>(&zfu.y);
        const float cov = sh_cov[nloc];
        float f0 = tanh_fast(fmaf(cov, wc4.x, __low2float(ha)  + dec4.x));
        float f1 = tanh_fast(fmaf(cov, wc4.y, __high2float(ha) + dec4.y));
        float f2 = tanh_fast(fmaf(cov, wc4.z, __low2float(hb)  + dec4.z));
        float f3 = tanh_fast(fmaf(cov, wc4.w, __high2float(hb) + dec4.w));
        float part = v4.x * f0 + v4.y * f1 + v4.z * f2 + v4.w * f3;
#pragma unroll
        for (int o = 16; o; o >>= 1) part += __shfl_xor_sync(0xffffffffu, part, o);
        float e = (sh_msk[nloc] > 0.f) ? part : -1e9f;
        if (lane == 0) g_e[b * N + nbase + nloc] = e;

        float nm = fmaxf(m, e);
        float sc = __expf(m - nm);
        float p  = __expf(e - nm);
        l = l * sc + p;
        ctx.x = fmaf(p, zv_c.x, ctx.x * sc);
        ctx.y = fmaf(p, zv_c.y, ctx.y * sc);
        ctx.z = fmaf(p, zv_c.z, ctx.z * sc);
        ctx.w = fmaf(p, zv_c.w, ctx.w * sc);
        m = nm;
    }

    sh_wctx[warp][lane * 4 + 0] = ctx.x;
    sh_wctx[warp][lane * 4 + 1] = ctx.y;
    sh_wctx[warp][lane * 4 + 2] = ctx.z;
    sh_wctx[warp][lane * 4 + 3] = ctx.w;
    if (lane == 0) { sh_wm[warp] = m; sh_wl[warp] = l; }
    __syncthreads();

    if (tid < 128) {
        float M = sh_wm[0];
#pragma unroll
        for (int w = 1; w < 8; ++w) M = fmaxf(M, sh_wm[w]);
        float acc = 0.f;
#pragma unroll
        for (int w = 0; w < 8; ++w) acc = fmaf(sh_wctx[w][tid], __expf(sh_wm[w] - M), acc);
        g_ctxp[((size_t)b * NSPLIT + split) * 128 + tid] = acc;
        if (tid == 0) {
            float L = 0.f;
#pragma unroll
            for (int w = 0; w < 8; ++w) L = fmaf(sh_wl[w], __expf(sh_wm[w] - M), L);
            g_mp[b * NSPLIT + split] = M;
            g_lp[b * NSPLIT + split] = L;
        }
    }
}

// --------- finish: combine + finalize + next LSTM; grid (NFIN, B) -----------
__global__ void __launch_bounds__(256) k_finish(
    int t, int T, float* __restrict__ out,
    const float* __restrict__ Wih, const float* __restrict__ Whh,
    const float* __restrict__ bih, const float* __restrict__ bhh,
    const float* __restrict__ Wx,  const float* __restrict__ battn)
{
    const int b = blockIdx.y;
    const int f = blockIdx.x;
    const int tid = threadIdx.x;
    __shared__ float sh_m[NSPLIT], sh_l[NSPLIT], sh_scale[NSPLIT];
    __shared__ float sh_red[256];
    __shared__ float sh_lstm[1664];

    if (tid < NSPLIT) {
        sh_m[tid] = g_mp[b * NSPLIT + tid];
        sh_l[tid] = g_lp[b * NSPLIT + tid];
    }
    __syncthreads();
    float M = sh_m[0];
#pragma unroll
    for (int s = 1; s < NSPLIT; ++s) M = fmaxf(M, sh_m[s]);
    if (tid < NSPLIT) sh_scale[tid] = __expf(sh_m[tid] - M);
    __syncthreads();
    float L = 0.f;
#pragma unroll
    for (int s = 0; s < NSPLIT; ++s) L = fmaf(sh_l[s], sh_scale[s], L);
    const float invL = 1.f / L;

    if (f == 0 && tid < 128) {
        float acc = 0.f;
#pragma unroll 8
        for (int s = 0; s < NSPLIT; ++s)
            acc = fmaf(g_ctxp[((size_t)b * NSPLIT + s) * 128 + tid], sh_scale[s], acc);
        float ct = acc * invL;
        out[((size_t)b * T + t) * DK + tid] = ct;
        g_s[b * DK + tid] = ct;
    }

    // finalize softmax slice, coverage update, coverage loss
    float* attn_out = out + (size_t)B * T * DK;
    const int n = f * (N / NFIN) + tid;   // N/NFIN == 256 == blockDim
    float e = g_e[b * N + n];
    float p = __expf(e - M) * invL;
    float cov = g_cov[b * N + n];
    float closs = fminf(p, cov);
    g_cov[b * N + n] = cov + p;
    attn_out[((size_t)b * T + t) * N + n] = p;

    sh_red[tid] = closs;
    __syncthreads();
#pragma unroll
    for (int o = 128; o; o >>= 1) {
        if (tid < o) sh_red[tid] += sh_red[tid + o];
        __syncthreads();
    }
    if (tid == 0) atomicAdd(&g_closs[b], sh_red[0]);

    // next-step LSTM + dec_fea (block f==0 only; overlaps other blocks' streaming)
    if (f == 0) {
        __syncthreads();
        lstm_and_dec(b, tid, Wih, Whh, bih, bhh, Wx, battn, sh_lstm);
    }
}

// ---------------- closs reduction ----------------
__global__ void k_closs(float* __restrict__ out, int T) {
    float val = (threadIdx.x < B) ? g_closs[threadIdx.x] : 0.f;
#pragma unroll
    for (int o = 16; o; o >>= 1) val += __shfl_xor_sync(0xffffffffu, val, o);
    if (threadIdx.x == 0)
        out[(size_t)B * T * DK + (size_t)B * T * N] = val / (float)B;
}

// ---------------- launch ----------------
extern "C" void kernel_launch(void* const* d_in, const int* in_sizes, int n_in,
                              void* d_out, int out_size) {
    const float* z     = (const float*)d_in[0];
    const float* mask  = (const float*)d_in[1];
    const float* h0    = (const float*)d_in[2];
    const float* c0    = (const float*)d_in[3];
    const float* Wih   = (const float*)d_in[4];
    const float* Whh   = (const float*)d_in[5];
    const float* bih   = (const float*)d_in[6];
    const float* bhh   = (const float*)d_in[7];
    const float* Wx    = (const float*)d_in[8];
    const float* Wz    = (const float*)d_in[9];
    const float* wc    = (const float*)d_in[10];
    const float* battn = (const float*)d_in[11];
    const float* v     = (const float*)d_in[12];
    float* out = (float*)d_out;

    const int T = (out_size - 1) / (B * (DK + N));  // 64

    k_init<<<512, 256>>>(h0, c0);
    k_zfea<<<1024, 256>>>(z, Wz);
    k_lstm0<<<B, 256>>>(Wih, Whh, bih, bhh, Wx, battn);
    for (int t = 0; t < T; ++t) {
        k_attn<<<dim3(NSPLIT, B), 256>>>(z, mask, wc, v);
        k_finish<<<dim3(NFIN, B), 256>>>(t, T, out, Wih, Whh, bih, bhh, Wx, battn);
    }
    k_closs<<<1, 32>>>(out, T);
}

// round 10
// speedup vs baseline: 1.0801x; 1.0801x over previous
#include <cuda_runtime.h>
#include <cuda_fp16.h>
#include <math.h>

constexpr int B  = 32;
constexpr int N  = 4096;
constexpr int DK = 128;
constexpr int H  = 128;
constexpr int A  = 128;
constexpr int NF = 16;            // CTAs per batch row
constexpr int CH = N / NF;        // 256 n per CTA
constexpr int GRID = NF * B;      // 512 CTAs (co-resident: 4/SM * 148 = 592)

// ---------------- scratch (device globals) ----------------
__device__ uint2 g_zfea[(size_t)B * N * 32];   // fp16 z@Wz features (4 halves/uint2)
__device__ uint2 g_z16 [(size_t)B * N * 32];   // fp16 copy of z
__device__ float g_dec[B * A];
__device__ float g_mp[B * NF], g_lp[B * NF];
__device__ float g_ctxp[(size_t)B * NF * DK];
__device__ float g_closs[B];
__device__ unsigned g_cnt;
__device__ volatile unsigned g_gen;

__device__ __forceinline__ float tanh_fast(float x) {
    float y;
    asm("tanh.approx.f32 %0, %1;" : "=f"(y) : "f"(x));
    return y;
}
__device__ __forceinline__ float sigf(float x) { return 1.f / (1.f + __expf(-x)); }

// ---------------- init (also resets barrier state every replay) ----------------
__global__ void k_init() {
    int i = blockIdx.x * blockDim.x + threadIdx.x;
    if (i < B) g_closs[i] = 0.f;
    if (i == B) { g_cnt = 0; g_gen = 0; }
}

// ---------------- z_fea = z @ W_z (fp16 out) + fp16 copy of z ----------------
__global__ void __launch_bounds__(256) k_zfea(const float* __restrict__ Z,
                                              const float* __restrict__ Wz) {
    __shared__ float z_s[128][17];
    __shared__ float w_s[16][128];
    const int tid  = threadIdx.x;
    const int rbase = blockIdx.x * 128;
    const int rowg = tid >> 4;
    const int colg = tid & 15;

    float acc[8][8];
#pragma unroll
    for (int i = 0; i < 8; ++i)
#pragma unroll
        for (int j = 0; j < 8; ++j) acc[i][j] = 0.f;

    for (int kk = 0; kk < 128; kk += 16) {
        {
            int r = tid >> 1;
            int c = (tid & 1) * 8;
            const float* src = Z + (size_t)(rbase + r) * 128 + kk + c;
            float4 a0 = *(const float4*)(src);
            float4 a1 = *(const float4*)(src + 4);
            z_s[r][c + 0] = a0.x; z_s[r][c + 1] = a0.y; z_s[r][c + 2] = a0.z; z_s[r][c + 3] = a0.w;
            z_s[r][c + 4] = a1.x; z_s[r][c + 5] = a1.y; z_s[r][c + 6] = a1.z; z_s[r][c + 7] = a1.w;
            // fp16 copy of z (each element loaded exactly once across kk loop)
            __half2 q0 = __floats2half2_rn(a0.x, a0.y);
            __half2 q1 = __floats2half2_rn(a0.z, a0.w);
            __half2 q2 = __floats2half2_rn(a1.x, a1.y);
            __half2 q3 = __floats2half2_rn(a1.z, a1.w);
            uint2 u0, u1;
            u0.x = *reinterpret_cast<unsigned*>(&q0);
            u0.y = *reinterpret_cast<unsigned*>(&q1);
            u1.x = *reinterpret_cast<unsigned*>(&q2);
            u1.y = *reinterpret_cast<unsigned*>(&q3);
            g_z16[(size_t)(rbase + r) * 32 + ((kk + c) >> 2)]     = u0;
            g_z16[(size_t)(rbase + r) * 32 + ((kk + c) >> 2) + 1] = u1;
        }
        {
            int kr = tid >> 4;
            int c  = (tid & 15) * 8;
            const float* src = Wz + (size_t)(kk + kr) * 128 + c;
            *(float4*)&w_s[kr][c]     = *(const float4*)(src);
            *(float4*)&w_s[kr][c + 4] = *(const float4*)(src + 4);
        }
        __syncthreads();
#pragma unroll
        for (int k = 0; k < 16; ++k) {
            float za[8];
#pragma unroll
            for (int i = 0; i < 8; ++i) za[i] = z_s[rowg * 8 + i][k];
            float4 wb0 = *(const float4*)&w_s[k][colg * 8];
            float4 wb1 = *(const float4*)&w_s[k][colg * 8 + 4];
            float wb[8] = {wb0.x, wb0.y, wb0.z, wb0.w, wb1.x, wb1.y, wb1.z, wb1.w};
#pragma unroll
            for (int i = 0; i < 8; ++i)
#pragma unroll
                for (int j = 0; j < 8; ++j) acc[i][j] = fmaf(za[i], wb[j], acc[i][j]);
        }
        __syncthreads();
    }
#pragma unroll
    for (int i = 0; i < 8; ++i) {
        size_t r = rbase + rowg * 8 + i;
        __half2 p0 = __floats2half2_rn(acc[i][0], acc[i][1]);
        __half2 p1 = __floats2half2_rn(acc[i][2], acc[i][3]);
        __half2 p2 = __floats2half2_rn(acc[i][4], acc[i][5]);
        __half2 p3 = __floats2half2_rn(acc[i][6], acc[i][7]);
        uint2 u0, u1;
        u0.x = *reinterpret_cast<unsigned*>(&p0);
        u0.y = *reinterpret_cast<unsigned*>(&p1);
        u1.x = *reinterpret_cast<unsigned*>(&p2);
        u1.y = *reinterpret_cast<unsigned*>(&p3);
        g_zfea[r * 32 + colg * 2]     = u0;
        g_zfea[r * 32 + colg * 2 + 1] = u1;
    }
}

// ======================= persistent decode kernel =======================
__global__ void __launch_bounds__(256, 4) k_decode(
    int T, float* __restrict__ out,
    const float* __restrict__ mask,
    const float* __restrict__ h0,  const float* __restrict__ c0,
    const float* __restrict__ Wih, const float* __restrict__ Whh,
    const float* __restrict__ bih, const float* __restrict__ bhh,
    const float* __restrict__ Wx,  const float* __restrict__ battn,
    const float* __restrict__ wc,  const float* __restrict__ v)
{
    const int f   = blockIdx.x;       // 0..NF-1
    const int b   = blockIdx.y;       // 0..B-1
    const int tid = threadIdx.x;
    const int lane = tid & 31;
    const int warp = tid >> 5;

    __shared__ float sh_cov[CH];      // persistent coverage for this chunk
    __shared__ float sh_msk[CH];
    __shared__ float sh_wm[8], sh_wl[8];
    __shared__ float sh_wctx[8][128];
    __shared__ float sh_scale[NF];
    __shared__ float sh_M, sh_invL;
    __shared__ float sh_s[128], sh_h[128], sh_c[128];   // LSTM state (f==0 only)
    __shared__ float sh_part[1024];
    __shared__ float sh_hn[128], sh_cn[128];

    // grid barrier (generation counter; g_cnt/g_gen zeroed by k_init)
    unsigned tgt = 0;
    auto gsync = [&]() {
        ++tgt;
        __syncthreads();
        if (tid == 0) {
            __threadfence();
            unsigned a = atomicAdd(&g_cnt, 1u);
            if (a == GRID - 1) {
                g_cnt = 0;
                __threadfence();
                g_gen = tgt;
            } else {
                while (g_gen < tgt) __nanosleep(64);
                __threadfence();
            }
        }
        __syncthreads();
    };

    // LSTM cell + dec_fea using persistent shared state (CTA f==0 only)
    auto lstm_dec = [&]() {
        const int j = tid & 127;
        const int half = tid >> 7;
        const float* xv = half ? sh_h : sh_s;
        const float* Wb = half ? Whh : Wih;
#pragma unroll
        for (int g = 0; g < 4; ++g) {
            const float4* wr = (const float4*)(Wb + (size_t)(g * 128 + j) * 128);
            float acc = 0.f;
#pragma unroll 8
            for (int d = 0; d < 32; ++d) {
                float4 w = wr[d];
                acc = fmaf(w.x, xv[4 * d + 0], acc);
                acc = fmaf(w.y, xv[4 * d + 1], acc);
                acc = fmaf(w.z, xv[4 * d + 2], acc);
                acc = fmaf(w.w, xv[4 * d + 3], acc);
            }
            sh_part[half * 512 + g * 128 + j] = acc;
        }
        __syncthreads();
        if (tid < 128) {
            float gi = sh_part[0   + tid] + sh_part[512 + tid] + bih[tid]       + bhh[tid];
            float gf = sh_part[128 + tid] + sh_part[640 + tid] + bih[128 + tid] + bhh[128 + tid];
            float gg = sh_part[256 + tid] + sh_part[768 + tid] + bih[256 + tid] + bhh[256 + tid];
            float go = sh_part[384 + tid] + sh_part[896 + tid] + bih[384 + tid] + bhh[384 + tid];
            float cn = sigf(gf) * sh_c[tid] + sigf(gi) * tanhf(gg);
            float hn = sigf(go) * tanhf(cn);
            sh_hn[tid] = hn; sh_cn[tid] = cn;
            sh_h[tid] = hn;  sh_c[tid] = cn;
        }
        __syncthreads();
        if (tid < 128) {
            float acc = battn[tid];
#pragma unroll 4
            for (int k = 0; k < 128; ++k) {
                acc = fmaf(sh_hn[k], Wx[(size_t)k * A + tid], acc);
                acc = fmaf(sh_cn[k], Wx[(size_t)(128 + k) * A + tid], acc);
            }
            g_dec[b * A + tid] = acc;
        }
    };

    // ---------- init ----------
    sh_msk[tid] = mask[b * N + f * CH + tid];
    sh_cov[tid] = 0.f;
    if (f == 0 && tid < 128) {
        sh_h[tid] = h0[b * H + tid];
        sh_c[tid] = c0[b * H + tid];
        sh_s[tid] = 0.f;
    }
    __syncthreads();
    if (f == 0) lstm_dec();         // initial dec_fea from (s=0, h0, c0)
    gsync();

    const float4 wc4 = ((const float4*)wc)[lane];
    const float4 v4  = ((const float4*)v)[lane];
    const uint2* zfb = g_zfea + (size_t)(b * N + f * CH + warp * 32) * 32 + lane;
    const uint2* zzb = g_z16  + (size_t)(b * N + f * CH + warp * 32) * 32 + lane;
    float* attn_out = out + (size_t)B * T * DK;

    float closs_acc = 0.f;

    for (int t = 0; t < T; ++t) {
        // dec_fea for this step (written by CTA (0,b); L1 not coherent -> ldcg)
        const float4 dec4 = __ldcg(((const float4*)(g_dec + b * A)) + lane);

        // ---- phase 1: online softmax + context partials over this chunk ----
        float m = -3.0e38f, l = 0.f;
        float4 ctx = {0.f, 0.f, 0.f, 0.f};
        float e_keep = 0.f;

        uint2 pf[4], pz[4];
#pragma unroll
        for (int k = 0; k < 4; ++k) { pf[k] = zfb[k * 32]; pz[k] = zzb[k * 32]; }

#pragma unroll
        for (int i = 0; i < 32; ++i) {
            uint2 zfu = pf[i & 3], zzu = pz[i & 3];
            if (i < 28) { pf[i & 3] = zfb[(i + 4) * 32]; pz[i & 3] = zzb[(i + 4) * 32]; }

            __half2 ha = *reinterpret_cast<__half2*>(&zfu.x);
            __half2 hb = *reinterpret_cast<__half2*>(&zfu.y);
            const float cov = sh_cov[warp * 32 + i];
            float f0 = tanh_fast(fmaf(cov, wc4.x, __low2float(ha)  + dec4.x));
            float f1 = tanh_fast(fmaf(cov, wc4.y, __high2float(ha) + dec4.y));
            float f2 = tanh_fast(fmaf(cov, wc4.z, __low2float(hb)  + dec4.z));
            float f3 = tanh_fast(fmaf(cov, wc4.w, __high2float(hb) + dec4.w));
            float part = v4.x * f0 + v4.y * f1 + v4.z * f2 + v4.w * f3;
#pragma unroll
            for (int o = 16; o; o >>= 1) part += __shfl_xor_sync(0xffffffffu, part, o);
            float e = (sh_msk[warp * 32 + i] > 0.f) ? part : -1e9f;
            if (lane == i) e_keep = e;

            float nm = fmaxf(m, e);
            float sc = __expf(m - nm);
            float p  = __expf(e - nm);
            l = l * sc + p;
            __half2 za = *reinterpret_cast<__half2*>(&zzu.x);
            __half2 zb2 = *reinterpret_cast<__half2*>(&zzu.y);
            ctx.x = fmaf(p, __low2float(za),  ctx.x * sc);
            ctx.y = fmaf(p, __high2float(za), ctx.y * sc);
            ctx.z = fmaf(p, __low2float(zb2),  ctx.z * sc);
            ctx.w = fmaf(p, __high2float(zb2), ctx.w * sc);
            m = nm;
        }

        sh_wctx[warp][lane * 4 + 0] = ctx.x;
        sh_wctx[warp][lane * 4 + 1] = ctx.y;
        sh_wctx[warp][lane * 4 + 2] = ctx.z;
        sh_wctx[warp][lane * 4 + 3] = ctx.w;
        if (lane == 0) { sh_wm[warp] = m; sh_wl[warp] = l; }
        __syncthreads();

        if (tid < 128) {
            float Mc = sh_wm[0];
#pragma unroll
            for (int w = 1; w < 8; ++w) Mc = fmaxf(Mc, sh_wm[w]);
            float acc = 0.f;
#pragma unroll
            for (int w = 0; w < 8; ++w) acc = fmaf(sh_wctx[w][tid], __expf(sh_wm[w] - Mc), acc);
            g_ctxp[((size_t)b * NF + f) * 128 + tid] = acc;
            if (tid == 0) {
                float Lc = 0.f;
#pragma unroll
                for (int w = 0; w < 8; ++w) Lc = fmaf(sh_wl[w], __expf(sh_wm[w] - Mc), Lc);
                g_mp[b * NF + f] = Mc;
                g_lp[b * NF + f] = Lc;
            }
        }
        gsync();

        // ---- phase 2: global M/L, finalize p, coverage, closs ----
        if (tid < NF) {
            float mv = __ldcg(&g_mp[b * NF + tid]);
            float lv = __ldcg(&g_lp[b * NF + tid]);
            float M = mv;
#pragma unroll
            for (int o = 8; o; o >>= 1) M = fmaxf(M, __shfl_xor_sync(0xffffu, M, o, 16));
            float sc = __expf(mv - M);
            float ls = lv * sc;
#pragma unroll
            for (int o = 8; o; o >>= 1) ls += __shfl_xor_sync(0xffffu, ls, o, 16);
            sh_scale[tid] = sc;
            if (tid == 0) { sh_M = M; sh_invL = 1.f / ls; }
        }
        __syncthreads();

        const float M = sh_M, invL = sh_invL;
        {
            float p = __expf(e_keep - M) * invL;
            float cov = sh_cov[tid];
            closs_acc += fminf(p, cov);
            sh_cov[tid] = cov + p;
            attn_out[((size_t)b * T + t) * N + f * CH + tid] = p;
        }

        // ---- phase 3: CTA (0,b) combines context, runs next LSTM + dec ----
        if (f == 0) {
            if (tid < 128) {
                float acc = 0.f;
#pragma unroll
                for (int s2 = 0; s2 < NF; ++s2)
                    acc = fmaf(__ldcg(&g_ctxp[((size_t)b * NF + s2) * 128 + tid]), sh_scale[s2], acc);
                float ct = acc * invL;
                out[((size_t)b * T + t) * DK + tid] = ct;
                sh_s[tid] = ct;
            }
            __syncthreads();
            lstm_dec();
        }
        gsync();
    }

    // ---- coverage-loss reduction ----
    sh_part[tid] = closs_acc;
    __syncthreads();
#pragma unroll
    for (int o = 128; o; o >>= 1) {
        if (tid < o) sh_part[tid] += sh_part[tid + o];
        __syncthreads();
    }
    if (tid == 0) atomicAdd(&g_closs[b], sh_part[0]);
    gsync();

    if (f == 0 && b == 0 && tid < 32) {
        float val = __ldcg(&g_closs[tid]);
#pragma unroll
        for (int o = 16; o; o >>= 1) val += __shfl_xor_sync(0xffffffffu, val, o);
        if (tid == 0)
            out[(size_t)B * T * DK + (size_t)B * T * N] = val / (float)B;
    }
}

// ---------------- launch ----------------
extern "C" void kernel_launch(void* const* d_in, const int* in_sizes, int n_in,
                              void* d_out, int out_size) {
    const float* z     = (const float*)d_in[0];
    const float* mask  = (const float*)d_in[1];
    const float* h0    = (const float*)d_in[2];
    const float* c0    = (const float*)d_in[3];
    const float* Wih   = (const float*)d_in[4];
    const float* Whh   = (const float*)d_in[5];
    const float* bih   = (const float*)d_in[6];
    const float* bhh   = (const float*)d_in[7];
    const float* Wx    = (const float*)d_in[8];
    const float* Wz    = (const float*)d_in[9];
    const float* wc    = (const float*)d_in[10];
    const float* battn = (const float*)d_in[11];
    const float* v     = (const float*)d_in[12];
    float* out = (float*)d_out;

    const int T = (out_size - 1) / (B * (DK + N));  // 64

    k_init<<<1, 64>>>();
    k_zfea<<<1024, 256>>>(z, Wz);
    k_decode<<<dim3(NF, B), 256>>>(T, out, mask, h0, c0,
                                   Wih, Whh, bih, bhh, Wx, battn, wc, v);
}